// round 7
// baseline (speedup 1.0000x reference)
#include <cuda_runtime.h>
#include <cuda_fp16.h>
#include <math.h>

// ---------------- problem constants ----------------
#define IMG     256
#define VIEWS   128
#define NDET    512
#define NS      364          // ceil(2R/STEP)+1, R = 256*sqrt(2)/2
#define SIDf    750.0f
#define SDDf    1250.0f
#define DET_ELT 1.2f
#define Rf      181.01933598375618f   // 256*sqrt(2)/2

// ---------------- packed padded images (fp16, full bilinear stencil / cell) ----
// normal layout, cell (i,j) [16B]:
//   { b0(i,j),   b1(i,j),   b0(i,j+1),   b1(i,j+1),
//     b0(i+1,j), b1(i+1,j), b0(i+1,j+1), b1(i+1,j+1) }   (fast axis = j)
// transposed layout swaps i and j (fast axis = i).
// PAD zero cells on every side -> clipped-range gathers are branch-free and
// out-of-image corners contribute exactly 0.
#define PAD 4
#define PW  272
#define PH  272
#define PWf 272.0f

__device__ uint4  g_pack [PH * PW];
__device__ uint4  g_packT[PH * PW];
__device__ float2 g_view[VIEWS];      // (cos beta, sin beta)

__device__ __forceinline__ float imgval(const float* x, int b, int i, int j) {
    if (i < 0 || i >= IMG || j < 0 || j >= IMG) return 0.f;
    return x[b * IMG * IMG + i * IMG + j];
}

// blockIdx.y = 0 -> normal layout, 1 -> transposed layout
__global__ void pack_kernel(const float* __restrict__ x) {
    int idx = blockIdx.x * blockDim.x + threadIdx.x;
    if (blockIdx.y == 0 && idx < VIEWS) {
        float beta = (float)((double)(2.8125 * (double)idx) * 0.017453292519943295);
        g_view[idx] = make_float2(cosf(beta), sinf(beta));
    }
    if (idx >= PH * PW) return;
    int row = idx / PW, col = idx % PW;

    __half h[8];
    if (blockIdx.y == 0) {
        int i = row - PAD, j = col - PAD;
        h[0] = __float2half_rn(imgval(x, 0, i,     j));
        h[1] = __float2half_rn(imgval(x, 1, i,     j));
        h[2] = __float2half_rn(imgval(x, 0, i,     j + 1));
        h[3] = __float2half_rn(imgval(x, 1, i,     j + 1));
        h[4] = __float2half_rn(imgval(x, 0, i + 1, j));
        h[5] = __float2half_rn(imgval(x, 1, i + 1, j));
        h[6] = __float2half_rn(imgval(x, 0, i + 1, j + 1));
        h[7] = __float2half_rn(imgval(x, 1, i + 1, j + 1));
        g_pack[idx] = *reinterpret_cast<uint4*>(h);
    } else {
        int j = row - PAD, i = col - PAD;
        h[0] = __float2half_rn(imgval(x, 0, i,     j));
        h[1] = __float2half_rn(imgval(x, 1, i,     j));
        h[2] = __float2half_rn(imgval(x, 0, i + 1, j));
        h[3] = __float2half_rn(imgval(x, 1, i + 1, j));
        h[4] = __float2half_rn(imgval(x, 0, i,     j + 1));
        h[5] = __float2half_rn(imgval(x, 1, i,     j + 1));
        h[6] = __float2half_rn(imgval(x, 0, i + 1, j + 1));
        h[7] = __float2half_rn(imgval(x, 1, i + 1, j + 1));
        g_packT[idx] = *reinterpret_cast<uint4*>(h);
    }
}

// ---------------- main projection kernel ----------------
// Block = 32 detectors x CHUNK s-segments (256 threads). One LDG.128 fetches
// the full bilinear stencil for both batches. Coordinates advance
// incrementally (2 FADD / sample); linear index computed with one exact
// fp32 fma + one F2I (no IMAD, no per-sample I2F).
#define CHUNK 8

__device__ __forceinline__ __half2 bilerp2(uint4 raw, __half2 gu2, __half2 gw2) {
    const __half2* h2 = reinterpret_cast<const __half2*>(&raw);
    __half2 top = __hfma2(gu2, __hsub2(h2[1], h2[0]), h2[0]);
    __half2 bot = __hfma2(gu2, __hsub2(h2[3], h2[2]), h2[2]);
    return __hfma2(gw2, __hsub2(bot, top), top);
}

__global__ void __launch_bounds__(256, 8) fpj_kernel(float* __restrict__ out) {
    const int lane  = threadIdx.x & 31;        // detector within group
    const int chunk = threadIdx.x >> 5;        // 0..7 segment id
    const int n = blockIdx.x * 32 + lane;      // detector index
    const int v = blockIdx.y;                  // view index

    // ---- geometry (float32 math matching the reference) ----
    float2 cs2 = g_view[v];
    float cb = cs2.x, sb = cs2.y;

    float u  = ((float)n - 255.5f) * DET_ELT;      // DET_OFF = 0
    float dx = -SDDf * cb - u * sb;                // det - src
    float dy = -SDDf * sb + u * cb;
    float inv = rsqrtf(dx * dx + dy * dy);
    dx *= inv; dy *= inv;                          // unit ray direction

    const float t0  = SIDf - Rf;
    float jx0 = fmaf(t0, dx, SIDf * cb) + 127.5f;  // jx at s=0
    float iy0 = 127.5f - fmaf(t0, dy, SIDf * sb);  // iy at s=0
    float djx = dx;                                // STEP=1, PIX=1
    float diy = -dy;

    // ---- clip s to where both coords stay in [-1.5, 256.5] (loss-free) ----
    const float LO = -1.5f, HI = 256.5f;
    float slo = 0.f, shi = (float)(NS - 1);
    {
        float s1 = (LO - jx0) / djx, s2 = (HI - jx0) / djx;
        slo = fmaxf(slo, fminf(s1, s2));
        shi = fminf(shi, fmaxf(s1, s2));
        s1 = (LO - iy0) / diy; s2 = (HI - iy0) / diy;
        slo = fmaxf(slo, fminf(s1, s2));
        shi = fminf(shi, fmaxf(s1, s2));
    }
    int is = (int)fminf(fmaxf(ceilf(slo),  0.f), (float)(NS - 1));
    int ie = (int)fminf(fmaxf(floorf(shi), -1.f), (float)(NS - 1));

    // ---- layout choice: detector tangent eu = (-sb, cb); pick the array whose
    // fast axis tracks the warp footprint (uniform per view, no divergence) ----
    bool trans = fabsf(cb) >= fabsf(sb);
    const uint4* __restrict__ pk = trans ? g_packT : g_pack;
    // fold PAD into the origins (lerp continuity makes 1-ulp floor flips benign)
    float u0 = (trans ? iy0 : jx0) + (float)PAD;   // fast coord
    float du =  trans ? diy : djx;
    float w0 = (trans ? jx0 : iy0) + (float)PAD;   // slow coord
    float dw =  trans ? djx : diy;

    // ---- this thread's sub-segment ----
    int len = ie - is + 1;
    int per = (len + CHUNK - 1) >> 3;              // ceil(len/8)
    int cs  = is + chunk * per;
    int ce  = cs + per - 1;
    if (ce > ie) ce = ie;
    int cnt = ce - cs + 1;                         // may be <= 0

    // running coordinates (incremental; drift <= ~1e-3 px over <=46 steps,
    // value-continuous across cell boundaries)
    float fu = fmaf((float)cs, du, u0);
    float fw = fmaf((float)cs, dw, w0);

    float acc0 = 0.f, acc1 = 0.f;

    // process pairs: one h2f convert + 2 FADD per TWO samples
    #pragma unroll 2
    for (; cnt >= 2; cnt -= 2) {
        float ufA = floorf(fu),  wfA = floorf(fw);
        float fuB = fu + du,     fwB = fw + dw;
        float ufB = floorf(fuB), wfB = floorf(fwB);

        // exact integer-valued fp32 math: base = wf*272 + uf  (< 2^24)
        int baseA = (int)fmaf(wfA, PWf, ufA);
        int baseB = (int)fmaf(wfB, PWf, ufB);

        uint4 rawA = pk[baseA];
        uint4 rawB = pk[baseB];

        __half2 guA = __float2half2_rn(fu  - ufA);
        __half2 gwA = __float2half2_rn(fw  - wfA);
        __half2 guB = __float2half2_rn(fuB - ufB);
        __half2 gwB = __float2half2_rn(fwB - wfB);

        __half2 rA = bilerp2(rawA, guA, gwA);
        __half2 rB = bilerp2(rawB, guB, gwB);
        float2 f = __half22float2(__hadd2(rA, rB));   // sum of 2 samples, both batches
        acc0 += f.x;
        acc1 += f.y;

        fu = fuB + du;
        fw = fwB + dw;
    }
    if (cnt > 0) {                                 // odd tail
        float uf = floorf(fu), wf = floorf(fw);
        uint4 raw = pk[(int)fmaf(wf, PWf, uf)];
        float2 f = __half22float2(bilerp2(raw,
                       __float2half2_rn(fu - uf), __float2half2_rn(fw - wf)));
        acc0 += f.x;
        acc1 += f.y;
    }

    // ---- reduce the CHUNK segment partials per detector ----
    __shared__ float r0[256];
    __shared__ float r1[256];
    r0[threadIdx.x] = acc0;
    r1[threadIdx.x] = acc1;
    __syncthreads();

    if (chunk == 0) {
        float s0 = 0.f, s1 = 0.f;
        #pragma unroll
        for (int c = 0; c < CHUNK; ++c) {
            s0 += r0[lane + 32 * c];
            s1 += r1[lane + 32 * c];
        }
        out[v * NDET + n]                = s0;    // STEP = 1.0 scale is a no-op
        out[VIEWS * NDET + v * NDET + n] = s1;
    }
}

// ---------------- launch ----------------
extern "C" void kernel_launch(void* const* d_in, const int* in_sizes, int n_in,
                              void* d_out, int out_size) {
    const float* x = (const float*)d_in[0];
    float* out = (float*)d_out;
    (void)in_sizes; (void)n_in; (void)out_size;

    pack_kernel<<<dim3((PH * PW + 255) / 256, 2), 256>>>(x);
    fpj_kernel<<<dim3(NDET / 32, VIEWS), 256>>>(out);
}